// round 8
// baseline (speedup 1.0000x reference)
#include <cuda_runtime.h>
#include <math.h>
#include <stdint.h>

#define NROWS   262144
#define NCTA    2048
#define ROWS_PER_CTA (NROWS / NCTA)     // 128
#define TILE_R  16                      // rows per pipeline stage (8 KB)
#define STAGES  3
#define NT      (ROWS_PER_CTA / TILE_R) // 8 tiles per CTA

// Unified weights, lane-major for conflict-free LDS.128:
// g_Wl[((sb*4+k)*32 + lane)*4 + o] = M[j][4*sb+k][4*q+o],  lane = 4*j+q.
// (M[j][d][ob]: y[ob] = sum_d x[d] * M[j][d][ob] for block j.)
__device__ float g_Wl[2048];

__global__ void bdla_prep(const float* __restrict__ W,
                          const float* __restrict__ s,
                          const float* __restrict__ U,
                          const float* __restrict__ V) {
    int e = threadIdx.x + blockIdx.x * blockDim.x;
    if (e >= 2048) return;
    int o    = e & 3;
    int idx  = e >> 2;          // [0,512)
    int lane = idx & 31;
    int sbk  = idx >> 5;        // [0,16)
    int sb   = sbk >> 2;
    int k    = sbk & 3;
    int j = lane >> 2, q = lane & 3;
    int d  = 4 * sb + k;        // input index within block
    int ob = 4 * q + o;         // output index within block
    float val;
    if (j == 0 || j == 3 || j == 6) {            // dense: y = x @ W^T
        int kk = j / 3;
        val = W[kk * 256 + ob * 16 + d];
    } else if (j == 1 || j == 4 || j == 7) {     // diagonal
        int kk = (j - 1) / 3;
        val = (d == ob) ? s[kk * 16 + d] : 0.0f;
    } else {                                     // lowrank: (V U^T)[d][ob]
        int kk = (j - 2) / 3;
        float acc = 0.0f;
        #pragma unroll
        for (int r = 0; r < 4; ++r)
            acc += V[kk * 64 + d * 4 + r] * U[kk * 64 + ob * 4 + r];
        val = acc;
    }
    g_Wl[e] = val;
}

__device__ __forceinline__ void cpa16(uint32_t dst, const float4* src) {
    asm volatile("cp.async.cg.shared.global [%0], [%1], 16;"
                 :: "r"(dst), "l"(src));
}
__device__ __forceinline__ void cpa_commit() {
    asm volatile("cp.async.commit_group;");
}
__device__ __forceinline__ void cpa_wait2() {
    asm volatile("cp.async.wait_group 2;");
}

__global__ void __launch_bounds__(128, 6)
bdla_main(const float4* __restrict__ x, float4* __restrict__ y) {
    __shared__ float4 sx[STAGES][TILE_R * 32];   // 3 x 8 KB
    __shared__ float4 sw[512];                   // 8 KB weights

    const int tid  = threadIdx.x;
    const int lane = tid & 31;
    const int wid  = tid >> 5;                   // 0..3
    const int j    = lane >> 2;                  // block id
    const unsigned ctaRow0 = blockIdx.x * ROWS_PER_CTA;

    // Stage weights into smem (visible after the first barrier below).
    {
        const float4* wg = (const float4*)g_Wl;
        #pragma unroll
        for (int i = 0; i < 4; ++i) sw[tid + 128 * i] = wg[tid + 128 * i];
    }

    const float4* gsrc0 = x + (size_t)ctaRow0 * 32;
    const uint32_t sbase = (uint32_t)__cvta_generic_to_shared(&sx[0][0]);

    // Prologue: prefetch tiles 0..STAGES-2.
    #pragma unroll
    for (int t = 0; t < STAGES - 1; ++t) {
        const uint32_t dst0 = sbase + (uint32_t)(t * TILE_R * 512);
        const float4* src0 = gsrc0 + t * TILE_R * 32;
        #pragma unroll
        for (int i = 0; i < 4; ++i)
            cpa16(dst0 + (tid + 128 * i) * 16u, src0 + tid + 128 * i);
        cpa_commit();
    }

    int stage = 0, pstage = STAGES - 1;
    #pragma unroll 1
    for (int t = 0; t < NT; ++t) {
        // Issue tile t+STAGES-1 into pstage; empty groups keep wait aligned.
        const int tp = t + STAGES - 1;
        if (tp < NT) {
            const uint32_t dst0 = sbase + (uint32_t)(pstage * TILE_R * 512);
            const float4* src0 = gsrc0 + tp * TILE_R * 32;
            #pragma unroll
            for (int i = 0; i < 4; ++i)
                cpa16(dst0 + (tid + 128 * i) * 16u, src0 + tid + 128 * i);
        }
        cpa_commit();
        cpa_wait2();              // my copies of tile t done
        __syncthreads();          // everyone's copies of tile t done

        const float4* tile = &sx[stage][0];

        // 4 rows per warp, batched: weights amortized, reductions ILP'd.
        float4 acc0 = {0,0,0,0}, acc1 = {0,0,0,0};
        float4 acc2 = {0,0,0,0}, acc3 = {0,0,0,0};

        #pragma unroll
        for (int sb = 0; sb < 4; ++sb) {
            const float4 w0 = sw[(sb * 4 + 0) * 32 + lane];
            const float4 w1 = sw[(sb * 4 + 1) * 32 + lane];
            const float4 w2 = sw[(sb * 4 + 2) * 32 + lane];
            const float4 w3 = sw[(sb * 4 + 3) * 32 + lane];
            const float4 a0 = tile[(wid * 4 + 0) * 32 + j * 4 + sb];
            const float4 a1 = tile[(wid * 4 + 1) * 32 + j * 4 + sb];
            const float4 a2 = tile[(wid * 4 + 2) * 32 + j * 4 + sb];
            const float4 a3 = tile[(wid * 4 + 3) * 32 + j * 4 + sb];
            #define ROWFMA(ACC, A)                                            \
                ACC.x = fmaf(A.x, w0.x, ACC.x); ACC.y = fmaf(A.x, w0.y, ACC.y);\
                ACC.z = fmaf(A.x, w0.z, ACC.z); ACC.w = fmaf(A.x, w0.w, ACC.w);\
                ACC.x = fmaf(A.y, w1.x, ACC.x); ACC.y = fmaf(A.y, w1.y, ACC.y);\
                ACC.z = fmaf(A.y, w1.z, ACC.z); ACC.w = fmaf(A.y, w1.w, ACC.w);\
                ACC.x = fmaf(A.z, w2.x, ACC.x); ACC.y = fmaf(A.z, w2.y, ACC.y);\
                ACC.z = fmaf(A.z, w2.z, ACC.z); ACC.w = fmaf(A.z, w2.w, ACC.w);\
                ACC.x = fmaf(A.w, w3.x, ACC.x); ACC.y = fmaf(A.w, w3.y, ACC.y);\
                ACC.z = fmaf(A.w, w3.z, ACC.z); ACC.w = fmaf(A.w, w3.w, ACC.w)
            ROWFMA(acc0, a0);
            ROWFMA(acc1, a1);
            ROWFMA(acc2, a2);
            ROWFMA(acc3, a3);
            #undef ROWFMA
        }

        // Four independent norm reductions (ILP across rows).
        float ss0 = acc0.x * acc0.x, ss1 = acc1.x * acc1.x;
        float ss2 = acc2.x * acc2.x, ss3 = acc3.x * acc3.x;
        ss0 = fmaf(acc0.y, acc0.y, ss0); ss1 = fmaf(acc1.y, acc1.y, ss1);
        ss2 = fmaf(acc2.y, acc2.y, ss2); ss3 = fmaf(acc3.y, acc3.y, ss3);
        ss0 = fmaf(acc0.z, acc0.z, ss0); ss1 = fmaf(acc1.z, acc1.z, ss1);
        ss2 = fmaf(acc2.z, acc2.z, ss2); ss3 = fmaf(acc3.z, acc3.z, ss3);
        ss0 = fmaf(acc0.w, acc0.w, ss0); ss1 = fmaf(acc1.w, acc1.w, ss1);
        ss2 = fmaf(acc2.w, acc2.w, ss2); ss3 = fmaf(acc3.w, acc3.w, ss3);
        #pragma unroll
        for (int m = 16; m >= 1; m >>= 1) {
            ss0 += __shfl_xor_sync(0xffffffffu, ss0, m);
            ss1 += __shfl_xor_sync(0xffffffffu, ss1, m);
            ss2 += __shfl_xor_sync(0xffffffffu, ss2, m);
            ss3 += __shfl_xor_sync(0xffffffffu, ss3, m);
        }
        const float i0 = rsqrtf(ss0), i1 = rsqrtf(ss1);
        const float i2 = rsqrtf(ss2), i3 = rsqrtf(ss3);

        const size_t gbase = (size_t)(ctaRow0 + t * TILE_R + wid * 4) * 32 + lane;
        y[gbase + 0 * 32] = make_float4(acc0.x * i0, acc0.y * i0, acc0.z * i0, acc0.w * i0);
        y[gbase + 1 * 32] = make_float4(acc1.x * i1, acc1.y * i1, acc1.z * i1, acc1.w * i1);
        y[gbase + 2 * 32] = make_float4(acc2.x * i2, acc2.y * i2, acc2.z * i2, acc2.w * i2);
        y[gbase + 3 * 32] = make_float4(acc3.x * i3, acc3.y * i3, acc3.z * i3, acc3.w * i3);

        __syncthreads();          // stage 'stage' safe to overwrite next iter

        stage  = (stage  == STAGES - 1) ? 0 : stage + 1;
        pstage = (pstage == STAGES - 1) ? 0 : pstage + 1;
    }
}

extern "C" void kernel_launch(void* const* d_in, const int* in_sizes, int n_in,
                              void* d_out, int out_size) {
    const float* x = (const float*)d_in[0];
    const float* W = (const float*)d_in[1];
    const float* s = (const float*)d_in[2];
    const float* U = (const float*)d_in[3];
    const float* V = (const float*)d_in[4];
    float* out = (float*)d_out;

    bdla_prep<<<8, 256>>>(W, s, U, V);
    bdla_main<<<NCTA, 128>>>((const float4*)x, (float4*)out);
}

// round 10
// speedup vs baseline: 1.0422x; 1.0422x over previous
#include <cuda_runtime.h>
#include <math.h>
#include <stdint.h>

#define NROWS   262144
#define NCTA    2048
#define ROWS_PER_CTA (NROWS / NCTA)     // 128
#define TILE_R  16                      // rows per pipeline stage (8 KB)
#define STAGES  5
#define NT      (ROWS_PER_CTA / TILE_R) // 8 tiles per CTA

// Unified per-block 16x16 matrices: g_M4[j*64 + d*4 + q] = M[j][d][4q..4q+3]
__device__ float4 g_M4[8 * 16 * 4];

__global__ void bdla_prep(const float* __restrict__ W,
                          const float* __restrict__ s,
                          const float* __restrict__ U,
                          const float* __restrict__ V) {
    float* gm = (float*)g_M4;
    for (int e = threadIdx.x + blockIdx.x * blockDim.x; e < 8 * 16 * 16;
         e += blockDim.x * gridDim.x) {
        int j = e >> 8;
        int rem = e & 255;
        int d = rem >> 4;
        int o = rem & 15;
        float val;
        if (j == 0 || j == 3 || j == 6) {            // dense: y = x @ W^T
            int k = j / 3;
            val = W[k * 256 + o * 16 + d];
        } else if (j == 1 || j == 4 || j == 7) {     // diagonal
            int k = (j - 1) / 3;
            val = (d == o) ? s[k * 16 + d] : 0.0f;
        } else {                                     // lowrank: (V U^T)[d][o]
            int k = (j - 2) / 3;
            float acc = 0.0f;
            #pragma unroll
            for (int r = 0; r < 4; ++r)
                acc += V[k * 64 + d * 4 + r] * U[k * 64 + o * 4 + r];
            val = acc;
        }
        gm[j * 256 + d * 16 + o] = val;
    }
}

__device__ __forceinline__ void cpa16(uint32_t dst, const float4* src) {
    asm volatile("cp.async.cg.shared.global [%0], [%1], 16;"
                 :: "r"(dst), "l"(src));
}
__device__ __forceinline__ void cpa_commit() {
    asm volatile("cp.async.commit_group;");
}
__device__ __forceinline__ void cpa_waitS2() {
    asm volatile("cp.async.wait_group %0;" :: "n"(STAGES - 2));
}

__global__ void __launch_bounds__(128)
bdla_main(const float4* __restrict__ x, float4* __restrict__ y) {
    __shared__ float4 sx[STAGES][TILE_R * 32];   // 5 x 8 KB = 40 KB

    const int tid  = threadIdx.x;
    const int lane = tid & 31;
    const int wid  = tid >> 5;                   // 0..3
    const int j    = lane >> 2;                  // block id
    const int q    = lane & 3;                   // output quad
    const unsigned ctaRow0 = blockIdx.x * ROWS_PER_CTA;

    // 64 weight registers per lane (R6-proven, no spills).
    float4 w[16];
    {
        const float4* Mp = g_M4 + (j << 6) + q;
        #pragma unroll
        for (int d = 0; d < 16; ++d) w[d] = Mp[d * 4];
    }

    const float4* gsrc0 = x + (size_t)ctaRow0 * 32;
    const uint32_t sbase = (uint32_t)__cvta_generic_to_shared(&sx[0][0]);

    // Prologue: prefetch tiles 0..STAGES-2 (one commit group per tile).
    #pragma unroll
    for (int t = 0; t < STAGES - 1; ++t) {
        const uint32_t dst0 = sbase + (uint32_t)(t * TILE_R * 512);
        const float4* src0 = gsrc0 + t * TILE_R * 32;
        #pragma unroll
        for (int i = 0; i < 4; ++i)
            cpa16(dst0 + (tid + 128 * i) * 16u, src0 + tid + 128 * i);
        cpa_commit();
    }

    int stage = 0;                // stage holding tile t
    int pstage = STAGES - 1;      // stage receiving tile t+STAGES-1
    #pragma unroll 1
    for (int t = 0; t < NT; ++t) {
        cpa_waitS2();             // tile t's copies (mine) complete
        __syncthreads();          // tile t visible to all; t-1 consumed by all

        // Prefetch tile t+STAGES-1 into tile (t-1)'s stage (safe after sync).
        const int tp = t + STAGES - 1;
        if (tp < NT) {
            const uint32_t dst0 = sbase + (uint32_t)(pstage * TILE_R * 512);
            const float4* src0 = gsrc0 + tp * TILE_R * 32;
            #pragma unroll
            for (int i = 0; i < 4; ++i)
                cpa16(dst0 + (tid + 128 * i) * 16u, src0 + tid + 128 * i);
        }
        cpa_commit();             // always commit (empty groups keep count)

        const float4* tile = &sx[stage][0];

        // Each warp computes 4 rows of the 16-row tile (unrolled -> the four
        // reduction butterflies interleave for ILP).
        #pragma unroll
        for (int k = 0; k < 4; ++k) {
            const int rit = wid + 4 * k;
            const float4* rowp = tile + rit * 32 + j * 4;

            float y0 = 0.f, y1 = 0.f, y2 = 0.f, y3 = 0.f;
            #pragma unroll
            for (int sb = 0; sb < 4; ++sb) {
                const float4 a = rowp[sb];           // quad-broadcast LDS.128
                const float4 w0 = w[4 * sb + 0];
                const float4 w1 = w[4 * sb + 1];
                const float4 w2 = w[4 * sb + 2];
                const float4 w3 = w[4 * sb + 3];
                y0 = fmaf(a.x, w0.x, y0); y1 = fmaf(a.x, w0.y, y1);
                y2 = fmaf(a.x, w0.z, y2); y3 = fmaf(a.x, w0.w, y3);
                y0 = fmaf(a.y, w1.x, y0); y1 = fmaf(a.y, w1.y, y1);
                y2 = fmaf(a.y, w1.z, y2); y3 = fmaf(a.y, w1.w, y3);
                y0 = fmaf(a.z, w2.x, y0); y1 = fmaf(a.z, w2.y, y1);
                y2 = fmaf(a.z, w2.z, y2); y3 = fmaf(a.z, w2.w, y3);
                y0 = fmaf(a.w, w3.x, y0); y1 = fmaf(a.w, w3.y, y1);
                y2 = fmaf(a.w, w3.z, y2); y3 = fmaf(a.w, w3.w, y3);
            }

            // Row L2 norm across all 32 lanes (shfl butterfly).
            float ss = y0 * y0;
            ss = fmaf(y1, y1, ss); ss = fmaf(y2, y2, ss); ss = fmaf(y3, y3, ss);
            #pragma unroll
            for (int m = 16; m >= 1; m >>= 1)
                ss += __shfl_xor_sync(0xffffffffu, ss, m);
            const float inv = rsqrtf(ss);

            const unsigned grow = ctaRow0 + (unsigned)(t * TILE_R + rit);
            y[(size_t)grow * 32 + lane] =
                make_float4(y0 * inv, y1 * inv, y2 * inv, y3 * inv);
        }

        stage  = (stage  == STAGES - 1) ? 0 : stage + 1;
        pstage = (pstage == STAGES - 1) ? 0 : pstage + 1;
    }
}

extern "C" void kernel_launch(void* const* d_in, const int* in_sizes, int n_in,
                              void* d_out, int out_size) {
    const float* x = (const float*)d_in[0];
    const float* W = (const float*)d_in[1];
    const float* s = (const float*)d_in[2];
    const float* U = (const float*)d_in[3];
    const float* V = (const float*)d_in[4];
    float* out = (float*)d_out;

    bdla_prep<<<8, 256>>>(W, s, U, V);
    bdla_main<<<NCTA, 128>>>((const float4*)x, (float4*)out);
}